// round 1
// baseline (speedup 1.0000x reference)
#include <cuda_runtime.h>
#include <math.h>

#define B_ 64
#define T_ 512
#define I_ 1024
#define H_ 1024
#define OUT1_ELEMS (B_*T_*H_)

#define NB_CTAS 128
#define BC 16     // batches per CTA
#define HC 32     // h rows per CTA
#define USTR 1028 // padded smem stride (conflict-free)
#define H3STR 1028

#define SMEM_FLOATS (32*USTR + 16*H3STR + 8*512 + 512)
#define SMEM_BYTES  (SMEM_FLOATS*4)

__device__ float g_xw[(size_t)B_*T_*H_];
__device__ unsigned int g_bar;

__global__ void init_kernel() { g_bar = 0u; }

// ---------------- Phase 1: xw = x @ W^T + bW  (M=B*T, N=H, K=I) ----------------
__global__ __launch_bounds__(256) void gemm_xw_kernel(
    const float* __restrict__ x, const float* __restrict__ W, const float* __restrict__ bW)
{
    __shared__ __align__(16) float As[16][128];
    __shared__ __align__(16) float Bs[16][128];
    const int tid = threadIdx.x;
    const int tile_m = blockIdx.y * 128;
    const int tile_n = blockIdx.x * 128;
    const int tn = tid & 15;   // n dir (8 cols each)
    const int tm = tid >> 4;   // m dir (8 rows each)

    float acc[8][8];
    #pragma unroll
    for (int i = 0; i < 8; i++)
        #pragma unroll
        for (int j = 0; j < 8; j++) acc[i][j] = 0.f;

    const int r0 = tid >> 2;   // 0..63
    const int c4 = tid & 3;    // 0..3

    for (int k0 = 0; k0 < I_; k0 += 16) {
        #pragma unroll
        for (int l = 0; l < 2; l++) {
            int r = r0 + l * 64;
            float4 va = *(const float4*)&x[(size_t)(tile_m + r) * I_ + k0 + c4 * 4];
            As[c4*4+0][r] = va.x; As[c4*4+1][r] = va.y;
            As[c4*4+2][r] = va.z; As[c4*4+3][r] = va.w;
            float4 vb = *(const float4*)&W[(size_t)(tile_n + r) * I_ + k0 + c4 * 4];
            Bs[c4*4+0][r] = vb.x; Bs[c4*4+1][r] = vb.y;
            Bs[c4*4+2][r] = vb.z; Bs[c4*4+3][r] = vb.w;
        }
        __syncthreads();
        #pragma unroll
        for (int k = 0; k < 16; k++) {
            float a[8], b[8];
            *(float4*)&a[0] = *(const float4*)&As[k][tm*8];
            *(float4*)&a[4] = *(const float4*)&As[k][tm*8+4];
            *(float4*)&b[0] = *(const float4*)&Bs[k][tn*8];
            *(float4*)&b[4] = *(const float4*)&Bs[k][tn*8+4];
            #pragma unroll
            for (int i = 0; i < 8; i++)
                #pragma unroll
                for (int j = 0; j < 8; j++)
                    acc[i][j] = fmaf(a[i], b[j], acc[i][j]);
        }
        __syncthreads();
    }

    float bias[8];
    #pragma unroll
    for (int j = 0; j < 8; j++) bias[j] = bW[tile_n + tn*8 + j];
    #pragma unroll
    for (int i = 0; i < 8; i++) {
        int m = tile_m + tm*8 + i;
        float4 o0 = make_float4(acc[i][0]+bias[0], acc[i][1]+bias[1],
                                acc[i][2]+bias[2], acc[i][3]+bias[3]);
        float4 o1 = make_float4(acc[i][4]+bias[4], acc[i][5]+bias[5],
                                acc[i][6]+bias[6], acc[i][7]+bias[7]);
        *(float4*)&g_xw[(size_t)m * H_ + tile_n + tn*8]     = o0;
        *(float4*)&g_xw[(size_t)m * H_ + tile_n + tn*8 + 4] = o1;
    }
}

// ---------------- Phase 2: persistent RNN recurrence ----------------
// Grid = 128 CTAs = 4 batch-groups x 32 h-groups. U slice (32x1024 fp32)
// lives in SMEM the whole kernel. One global barrier per timestep.
__global__ __launch_bounds__(256) void rnn_kernel(
    const float* __restrict__ U, const float* __restrict__ bU, float* __restrict__ out)
{
    extern __shared__ float sm[];
    float* sUs    = sm;                          // 32 * 1028
    float* sH3    = sm + 32*USTR;                // 16 * 1028
    float* sPart  = sm + 32*USTR + 16*H3STR;     // 8 * 512
    float* sState = sPart + 8*512;               // 512

    const int tid = threadIdx.x;
    const int cta = blockIdx.x;
    const int bg = cta >> 5;       // 0..3
    const int hg = cta & 31;       // 0..31
    const int b_base = bg * BC;
    const int h_base = hg * HC;

    // Load U slice into smem (rows h_base..h_base+31), padded stride
    #pragma unroll
    for (int q = 0; q < 32; q++) {
        int idx4 = tid + q * 256;          // 0..8191 float4s
        int hi = idx4 >> 8;                // 0..31
        int k4 = idx4 & 255;               // 0..255
        float4 v = *(const float4*)&U[(size_t)(h_base + hi) * H_ + k4 * 4];
        *(float4*)&sUs[hi * USTR + k4 * 4] = v;
    }
    sState[tid] = 0.f;
    sState[tid + 256] = 0.f;
    const float my_bu = bU[h_base + (tid & 31)];
    __syncthreads();

    const int w  = tid >> 5;   // warp id: owns k in [w*128, w*128+128)
    const int l  = tid & 31;
    const int lb = l & 3;      // 4 batch groups of 4
    const int lh = l >> 2;     // 8 h groups of 4
    const float* h3p_base = sH3 + (lb * 4) * H3STR + w * 128;
    const float* up_base  = sUs + (lh * 4) * USTR  + w * 128;

    for (int t = 0; t < T_; t++) {
        // (a) h3 = tanh(xw[t] + state); write h3 slice into out1 (and out2 on last step)
        #pragma unroll
        for (int rep = 0; rep < 2; rep++) {
            int o  = tid + rep * 256;      // o = bi*32 + hi
            int bi = o >> 5;
            int hi = o & 31;
            size_t gidx = ((size_t)(b_base + bi) * T_ + t) * H_ + h_base + hi;
            float v   = g_xw[gidx] + sState[o];
            float h3v = tanhf(v);
            out[gidx] = h3v;
            if (t == T_ - 1)
                out[(size_t)OUT1_ELEMS + (size_t)(b_base + bi) * H_ + h_base + hi] = h3v;
        }

        // (b) grid-wide barrier (monotonic counter)
        __syncthreads();
        if (tid == 0) {
            __threadfence();
            atomicAdd(&g_bar, 1u);
            unsigned target = (unsigned)NB_CTAS * (unsigned)(t + 1);
            while (*((volatile unsigned int*)&g_bar) < target) { }
            __threadfence();
        }
        __syncthreads();

        // (c) gather full h3[t] rows for our 16 batches into smem
        #pragma unroll
        for (int q = 0; q < 16; q++) {
            int idx4 = tid + q * 256;     // 0..4095 float4s
            int bi = idx4 >> 8;           // 0..15
            int k4 = idx4 & 255;
            float4 v = *(const float4*)&out[((size_t)(b_base + bi) * T_ + t) * H_ + k4 * 4];
            *(float4*)&sH3[bi * H3STR + k4 * 4] = v;
        }
        __syncthreads();

        // (d) matvec: state_next[bi][hi] = sum_k h3[bi][k] * U[hi][k]
        // warp splits k; lane tile = 4 batches x 4 h
        float c[4][4];
        #pragma unroll
        for (int i = 0; i < 4; i++)
            #pragma unroll
            for (int j = 0; j < 4; j++) c[i][j] = 0.f;

        #pragma unroll 8
        for (int it = 0; it < 32; it++) {
            float4 hv[4], uv[4];
            #pragma unroll
            for (int i = 0; i < 4; i++)
                hv[i] = *(const float4*)(h3p_base + i * H3STR + it * 4);
            #pragma unroll
            for (int j = 0; j < 4; j++)
                uv[j] = *(const float4*)(up_base + j * USTR + it * 4);
            #pragma unroll
            for (int i = 0; i < 4; i++)
                #pragma unroll
                for (int j = 0; j < 4; j++) {
                    c[i][j] = fmaf(hv[i].x, uv[j].x, c[i][j]);
                    c[i][j] = fmaf(hv[i].y, uv[j].y, c[i][j]);
                    c[i][j] = fmaf(hv[i].z, uv[j].z, c[i][j]);
                    c[i][j] = fmaf(hv[i].w, uv[j].w, c[i][j]);
                }
        }
        #pragma unroll
        for (int i = 0; i < 4; i++)
            *(float4*)&sPart[w * 512 + (lb * 4 + i) * 32 + lh * 4] =
                make_float4(c[i][0], c[i][1], c[i][2], c[i][3]);
        __syncthreads();

        // reduce 8 warp partials + bias -> next state
        #pragma unroll
        for (int rep = 0; rep < 2; rep++) {
            int o = tid + rep * 256;
            float s = 0.f;
            #pragma unroll
            for (int w2 = 0; w2 < 8; w2++) s += sPart[w2 * 512 + o];
            sState[o] = s + my_bu;
        }
        __syncthreads();
    }
}

extern "C" void kernel_launch(void* const* d_in, const int* in_sizes, int n_in,
                              void* d_out, int out_size)
{
    const float* x  = (const float*)d_in[0];
    const float* W  = (const float*)d_in[1];
    const float* bW = (const float*)d_in[2];
    const float* U  = (const float*)d_in[3];
    const float* bU = (const float*)d_in[4];
    float* out = (float*)d_out;

    init_kernel<<<1, 1>>>();

    dim3 g1(H_ / 128, (B_ * T_) / 128);
    gemm_xw_kernel<<<g1, 256>>>(x, W, bW);

    cudaFuncSetAttribute(rnn_kernel, cudaFuncAttributeMaxDynamicSharedMemorySize, SMEM_BYTES);
    rnn_kernel<<<NB_CTAS, 256, SMEM_BYTES>>>(U, bU, out);
}

// round 4
// speedup vs baseline: 1.2301x; 1.2301x over previous
#include <cuda_runtime.h>
#include <cuda_bf16.h>
#include <math.h>
#include <stdint.h>

#define B_ 64
#define T_ 512
#define I_ 1024
#define H_ 1024
#define OUT1_ELEMS (B_*T_*H_)

// ---------------- device scratch ----------------
__device__ float g_xw[(size_t)B_*T_*H_];
__device__ __nv_bfloat16 g_xhi[(size_t)B_*T_*I_];
__device__ __nv_bfloat16 g_xlo[(size_t)B_*T_*I_];
__device__ __nv_bfloat16 g_whi[(size_t)H_*I_];
__device__ __nv_bfloat16 g_wlo[(size_t)H_*I_];
__device__ unsigned int g_bar4[4];

// ---------------- PTX helpers (sm_80-era only; compiles under compute_103) ----
__device__ __forceinline__ uint32_t smem_u32(const void* p) {
    uint32_t a;
    asm("{ .reg .u64 t; cvta.to.shared.u64 t, %1; cvt.u32.u64 %0, t; }" : "=r"(a) : "l"(p));
    return a;
}
#define CP_ASYNC16(s, g) \
    asm volatile("cp.async.cg.shared.global [%0], [%1], 16;" :: "r"(s), "l"(g) : "memory")
#define CP_COMMIT() asm volatile("cp.async.commit_group;" ::: "memory")
#define CP_WAIT(N)  asm volatile("cp.async.wait_group %0;" :: "n"(N) : "memory")

__device__ __forceinline__ void ldsm4(uint32_t& r0, uint32_t& r1, uint32_t& r2, uint32_t& r3,
                                      uint32_t addr) {
    asm volatile("ldmatrix.sync.aligned.m8n8.x4.shared.b16 {%0,%1,%2,%3}, [%4];"
                 : "=r"(r0), "=r"(r1), "=r"(r2), "=r"(r3) : "r"(addr));
}
__device__ __forceinline__ void mma16816(float* d, const uint32_t* a, const uint32_t* b) {
    asm volatile("mma.sync.aligned.m16n8k16.row.col.f32.bf16.bf16.f32 "
                 "{%0,%1,%2,%3}, {%4,%5,%6,%7}, {%8,%9}, {%0,%1,%2,%3};"
                 : "+f"(d[0]), "+f"(d[1]), "+f"(d[2]), "+f"(d[3])
                 : "r"(a[0]), "r"(a[1]), "r"(a[2]), "r"(a[3]), "r"(b[0]), "r"(b[1]));
}
__device__ __forceinline__ uint32_t sw128(uint32_t off) { return off ^ ((off >> 3) & 0x70); }

// ---------------- fp32 -> bf16 hi/lo split ----------------
__global__ __launch_bounds__(256) void conv_kernel(const float* __restrict__ src,
                                                   int which, int n4)
{
    int i = blockIdx.x * 256 + threadIdx.x;
    if (which == 0 && blockIdx.x == 0 && threadIdx.x < 4) g_bar4[threadIdx.x] = 0u;
    if (i >= n4) return;
    __nv_bfloat16* hi = which ? g_whi : g_xhi;
    __nv_bfloat16* lo = which ? g_wlo : g_xlo;
    float4 v = ((const float4*)src)[i];
    __nv_bfloat16 h0 = __float2bfloat16(v.x), h1 = __float2bfloat16(v.y);
    __nv_bfloat16 h2 = __float2bfloat16(v.z), h3 = __float2bfloat16(v.w);
    __nv_bfloat16 l0 = __float2bfloat16(v.x - __bfloat162float(h0));
    __nv_bfloat16 l1 = __float2bfloat16(v.y - __bfloat162float(h1));
    __nv_bfloat16 l2 = __float2bfloat16(v.z - __bfloat162float(h2));
    __nv_bfloat16 l3 = __float2bfloat16(v.w - __bfloat162float(h3));
    __nv_bfloat162* hp = (__nv_bfloat162*)hi;
    __nv_bfloat162* lp = (__nv_bfloat162*)lo;
    hp[2*i]   = __nv_bfloat162{h0, h1};
    hp[2*i+1] = __nv_bfloat162{h2, h3};
    lp[2*i]   = __nv_bfloat162{l0, l1};
    lp[2*i+1] = __nv_bfloat162{l2, l3};
}

// ---------------- Phase 1: HMMA GEMM ----------------
// D[32768,1024] = Xhi*Whi^T + Xlo*Whi^T + Xhi*Wlo^T + bW
// CTA 128x128, BK=64, 3-stage cp.async, 8 warps (4m x 2n), warp tile 32x64.
#define BK 64
#define NCHUNK 48
#define STG_BYTES 32768   // A 16KB + B 16KB
#define GEMM_SMEM (3*STG_BYTES)

__device__ __forceinline__ void load_chunk(uint32_t sbase, const __nv_bfloat16* A,
                                           const __nv_bfloat16* Bs, int m0, int n0,
                                           int k0, int tid)
{
    #pragma unroll
    for (int j = 0; j < 4; j++) {
        int idx = tid + j * 256;
        int r = idx >> 3, c = idx & 7;
        uint32_t off = sw128((uint32_t)(r * 128 + c * 16));
        CP_ASYNC16(sbase + off, A + (size_t)(m0 + r) * 1024 + k0 + c * 8);
    }
    #pragma unroll
    for (int j = 0; j < 4; j++) {
        int idx = tid + j * 256;
        int r = idx >> 3, c = idx & 7;
        uint32_t off = sw128((uint32_t)(r * 128 + c * 16));
        CP_ASYNC16(sbase + 16384 + off, Bs + (size_t)(n0 + r) * 1024 + k0 + c * 8);
    }
}

__global__ __launch_bounds__(256, 2) void gemm_mma_kernel(const float* __restrict__ bW)
{
    extern __shared__ __align__(1024) char smem[];
    const uint32_t smem_b = smem_u32(smem);
    const int tid = threadIdx.x;
    const int wid = tid >> 5;
    const int lane = tid & 31;
    const int n0 = blockIdx.x * 128;
    const int m0 = blockIdx.y * 128;
    const int wm = (wid & 3) * 32;   // warp m offset
    const int wn = (wid >> 2) * 64;  // warp n offset

    float acc[2][8][4];
    #pragma unroll
    for (int i = 0; i < 2; i++)
        #pragma unroll
        for (int j = 0; j < 8; j++)
            #pragma unroll
            for (int q = 0; q < 4; q++) acc[i][j][q] = 0.f;

    // prologue: chunks 0,1
    #pragma unroll
    for (int c = 0; c < 2; c++) {
        load_chunk(smem_b + c * STG_BYTES, g_xhi, g_whi, m0, n0, c * 64, tid);
        CP_COMMIT();
    }

    // precomputed ldmatrix base offsets (kk=0)
    uint32_t aoff[2], boff[4];
    #pragma unroll
    for (int mi = 0; mi < 2; mi++) {
        uint32_t row = wm + mi * 16 + (lane & 15);
        aoff[mi] = (uint32_t)(row * 128 + (lane >> 4) * 16);
    }
    #pragma unroll
    for (int ni = 0; ni < 4; ni++) {
        uint32_t nrow = wn + ni * 16 + (lane & 7) + ((lane >> 4) & 1) * 8;
        uint32_t kc = (lane >> 3) & 1;
        boff[ni] = (uint32_t)(16384 + nrow * 128 + kc * 16);
    }

    for (int c = 0; c < NCHUNK; c++) {
        CP_WAIT(1);
        __syncthreads();
        if (c + 2 < NCHUNK) {
            int cn = c + 2;
            int p = cn >> 4;
            int k0 = (cn & 15) * 64;
            const __nv_bfloat16* As = (p == 1) ? g_xlo : g_xhi;
            const __nv_bfloat16* Bs = (p == 2) ? g_wlo : g_whi;
            load_chunk(smem_b + (cn % 3) * STG_BYTES, As, Bs, m0, n0, k0, tid);
        }
        CP_COMMIT();

        const uint32_t sb = smem_b + (c % 3) * STG_BYTES;
        #pragma unroll
        for (int kk = 0; kk < 4; kk++) {
            uint32_t a[2][4], b[8][2];
            #pragma unroll
            for (int mi = 0; mi < 2; mi++)
                ldsm4(a[mi][0], a[mi][1], a[mi][2], a[mi][3],
                      sb + sw128(aoff[mi] + kk * 32));
            #pragma unroll
            for (int ni = 0; ni < 4; ni++)
                ldsm4(b[2*ni][0], b[2*ni][1], b[2*ni+1][0], b[2*ni+1][1],
                      sb + sw128(boff[ni] + kk * 32));
            #pragma unroll
            for (int mi = 0; mi < 2; mi++)
                #pragma unroll
                for (int nj = 0; nj < 8; nj++)
                    mma16816(acc[mi][nj], a[mi], b[nj]);
        }
        __syncthreads();
    }

    // epilogue: direct stores + bias
    #pragma unroll
    for (int mi = 0; mi < 2; mi++) {
        int row0 = m0 + wm + mi * 16 + (lane >> 2);
        #pragma unroll
        for (int nj = 0; nj < 8; nj++) {
            int col = n0 + wn + nj * 8 + 2 * (lane & 3);
            float b0 = __ldg(&bW[col]), b1 = __ldg(&bW[col + 1]);
            *(float2*)&g_xw[(size_t)row0 * H_ + col] =
                make_float2(acc[mi][nj][0] + b0, acc[mi][nj][1] + b1);
            *(float2*)&g_xw[(size_t)(row0 + 8) * H_ + col] =
                make_float2(acc[mi][nj][2] + b0, acc[mi][nj][3] + b1);
        }
    }
}

// ---------------- Phase 2: persistent RNN recurrence ----------------
#define NB_CTAS 128
#define BC 16
#define HC 32
#define USTR 1028
#define H3STR 1028
#define SMEM_FLOATS (32*USTR + 16*H3STR + 8*512 + 512)
#define SMEM_BYTES  (SMEM_FLOATS*4)

__global__ __launch_bounds__(256) void rnn_kernel(
    const float* __restrict__ U, const float* __restrict__ bU, float* __restrict__ out)
{
    extern __shared__ float sm[];
    float* sUs    = sm;
    float* sH3    = sm + 32*USTR;
    float* sPart  = sm + 32*USTR + 16*H3STR;
    float* sState = sPart + 8*512;

    const int tid = threadIdx.x;
    const int cta = blockIdx.x;
    const int bg = cta >> 5;
    const int hg = cta & 31;
    const int b_base = bg * BC;
    const int h_base = hg * HC;

    #pragma unroll
    for (int q = 0; q < 32; q++) {
        int idx4 = tid + q * 256;
        int hi = idx4 >> 8;
        int k4 = idx4 & 255;
        float4 v = *(const float4*)&U[(size_t)(h_base + hi) * H_ + k4 * 4];
        *(float4*)&sUs[hi * USTR + k4 * 4] = v;
    }
    sState[tid] = 0.f;
    sState[tid + 256] = 0.f;
    const float my_bu = bU[h_base + (tid & 31)];
    __syncthreads();

    const int w  = tid >> 5;
    const int l  = tid & 31;
    const int lb = l & 3;
    const int lh = l >> 2;
    const float* h3p_base = sH3 + (lb * 4) * H3STR + w * 128;
    const float* up_base  = sUs + (lh * 4) * USTR  + w * 128;

    for (int t = 0; t < T_; t++) {
        #pragma unroll
        for (int rep = 0; rep < 2; rep++) {
            int o  = tid + rep * 256;
            int bi = o >> 5;
            int hi = o & 31;
            size_t gidx = ((size_t)(b_base + bi) * T_ + t) * H_ + h_base + hi;
            float v   = g_xw[gidx] + sState[o];
            float h3v = tanhf(v);
            out[gidx] = h3v;
            if (t == T_ - 1)
                out[(size_t)OUT1_ELEMS + (size_t)(b_base + bi) * H_ + h_base + hi] = h3v;
        }

        __syncthreads();
        if (tid == 0) {
            __threadfence();
            atomicAdd(&g_bar4[bg], 1u);
            unsigned target = 32u * (unsigned)(t + 1);
            while (*((volatile unsigned int*)&g_bar4[bg]) < target) { }
            __threadfence();
        }
        __syncthreads();

        #pragma unroll
        for (int q = 0; q < 16; q++) {
            int idx4 = tid + q * 256;
            int bi = idx4 >> 8;
            int k4 = idx4 & 255;
            float4 v = *(const float4*)&out[((size_t)(b_base + bi) * T_ + t) * H_ + k4 * 4];
            *(float4*)&sH3[bi * H3STR + k4 * 4] = v;
        }
        __syncthreads();

        float c[4][4];
        #pragma unroll
        for (int i = 0; i < 4; i++)
            #pragma unroll
            for (int j = 0; j < 4; j++) c[i][j] = 0.f;

        #pragma unroll 8
        for (int it = 0; it < 32; it++) {
            float4 hv[4], uv[4];
            #pragma unroll
            for (int i = 0; i < 4; i++)
                hv[i] = *(const float4*)(h3p_base + i * H3STR + it * 4);
            #pragma unroll
            for (int j = 0; j < 4; j++)
                uv[j] = *(const float4*)(up_base + j * USTR + it * 4);
            #pragma unroll
            for (int i = 0; i < 4; i++)
                #pragma unroll
                for (int j = 0; j < 4; j++) {
                    c[i][j] = fmaf(hv[i].x, uv[j].x, c[i][j]);
                    c[i][j] = fmaf(hv[i].y, uv[j].y, c[i][j]);
                    c[i][j] = fmaf(hv[i].z, uv[j].z, c[i][j]);
                    c[i][j] = fmaf(hv[i].w, uv[j].w, c[i][j]);
                }
        }
        #pragma unroll
        for (int i = 0; i < 4; i++)
            *(float4*)&sPart[w * 512 + (lb * 4 + i) * 32 + lh * 4] =
                make_float4(c[i][0], c[i][1], c[i][2], c[i][3]);
        __syncthreads();

        #pragma unroll
        for (int rep = 0; rep < 2; rep++) {
            int o = tid + rep * 256;
            float s = 0.f;
            #pragma unroll
            for (int w2 = 0; w2 < 8; w2++) s += sPart[w2 * 512 + o];
            sState[o] = s + my_bu;
        }
        __syncthreads();
    }
}

extern "C" void kernel_launch(void* const* d_in, const int* in_sizes, int n_in,
                              void* d_out, int out_size)
{
    const float* x  = (const float*)d_in[0];
    const float* W  = (const float*)d_in[1];
    const float* bW = (const float*)d_in[2];
    const float* U  = (const float*)d_in[3];
    const float* bU = (const float*)d_in[4];
    float* out = (float*)d_out;

    conv_kernel<<<(B_*T_*I_/4 + 255)/256, 256>>>(x, 0, B_*T_*I_/4);
    conv_kernel<<<(H_*I_/4 + 255)/256, 256>>>(W, 1, H_*I_/4);

    cudaFuncSetAttribute(gemm_mma_kernel, cudaFuncAttributeMaxDynamicSharedMemorySize, GEMM_SMEM);
    dim3 g1(H_ / 128, (B_ * T_) / 128);
    gemm_mma_kernel<<<g1, 256, GEMM_SMEM>>>(bW);

    cudaFuncSetAttribute(rnn_kernel, cudaFuncAttributeMaxDynamicSharedMemorySize, SMEM_BYTES);
    rnn_kernel<<<NB_CTAS, 256, SMEM_BYTES>>>(U, bU, out);
}